// round 2
// baseline (speedup 1.0000x reference)
#include <cuda_runtime.h>
#include <cuda_bf16.h>

// AMSoftmaxLoss: score (2048 x 50257) fp32, labels (2048) int32 in {0,1}
// L_i = num_i - log(exp(num_i) + sum_j exp(S*score_ij) - exp(S*target_i))
// out  = -mean(L),  S=30, m = {0:0.1, 1:0.4}[label]

#define NROWS 2048
#define CCOLS 50257
#define BLK   256

__device__ float g_rowL[NROWS];

__device__ __forceinline__ float ex2f(float x) {
    float y;
    asm("ex2.approx.ftz.f32 %0, %1;" : "=f"(y) : "f"(x));
    return y;
}

__global__ __launch_bounds__(BLK) void amsm_row_kernel(
    const float* __restrict__ score,
    const int* __restrict__ labels)
{
    const int row = blockIdx.x;
    const float* __restrict__ p = score + (size_t)row * CCOLS;

    const float SL2E = 30.0f * 1.44269504088896340736f; // S * log2(e)

    // Strided scan with 4 independent accumulators for MLP.
    float s0 = 0.f, s1 = 0.f, s2 = 0.f, s3 = 0.f;
    int j = threadIdx.x;
    #pragma unroll 2
    for (; j + 3 * BLK < CCOLS; j += 4 * BLK) {
        float x0 = p[j];
        float x1 = p[j + BLK];
        float x2 = p[j + 2 * BLK];
        float x3 = p[j + 3 * BLK];
        s0 += ex2f(SL2E * x0);
        s1 += ex2f(SL2E * x1);
        s2 += ex2f(SL2E * x2);
        s3 += ex2f(SL2E * x3);
    }
    for (; j < CCOLS; j += BLK)
        s0 += ex2f(SL2E * p[j]);

    float sum = (s0 + s1) + (s2 + s3);

    // Block reduction
    __shared__ float red[BLK];
    red[threadIdx.x] = sum;
    __syncthreads();
    #pragma unroll
    for (int off = BLK / 2; off >= 32; off >>= 1) {
        if (threadIdx.x < off) red[threadIdx.x] += red[threadIdx.x + off];
        __syncthreads();
    }
    if (threadIdx.x < 32) {
        float v = red[threadIdx.x];
        #pragma unroll
        for (int off = 16; off > 0; off >>= 1)
            v += __shfl_down_sync(0xFFFFFFFFu, v, off);
        if (threadIdx.x == 0) {
            int lab = labels[row] & 1;             // 0 or 1
            float m = lab ? 0.4f : 0.1f;
            float t = p[lab];                      // target logit
            float num = 30.0f * (t - m);
            float excl = v - ex2f(SL2E * t);       // sum minus target term
            float denom = ex2f(num * 1.44269504088896340736f) + excl;
            g_rowL[row] = num - logf(denom);
        }
    }
}

__global__ __launch_bounds__(1024) void amsm_final_kernel(float* __restrict__ out)
{
    __shared__ double red[1024];
    double acc = 0.0;
    for (int i = threadIdx.x; i < NROWS; i += 1024)
        acc += (double)g_rowL[i];
    red[threadIdx.x] = acc;
    __syncthreads();
    #pragma unroll
    for (int off = 512; off > 0; off >>= 1) {
        if (threadIdx.x < off) red[threadIdx.x] += red[threadIdx.x + off];
        __syncthreads();
    }
    if (threadIdx.x == 0)
        out[0] = (float)(-red[0] / (double)NROWS);
}

extern "C" void kernel_launch(void* const* d_in, const int* in_sizes, int n_in,
                              void* d_out, int out_size)
{
    const float* score = (const float*)d_in[0];
    const int* labels = (const int*)d_in[1];
    float* out = (float*)d_out;

    amsm_row_kernel<<<NROWS, BLK>>>(score, labels);
    amsm_final_kernel<<<1, 1024>>>(out);
}

// round 3
// speedup vs baseline: 1.0595x; 1.0595x over previous
#include <cuda_runtime.h>
#include <cuda_bf16.h>

// AMSoftmaxLoss: score (2048 x 50257) fp32, labels (2048) int32 in {0,1}
// L_i = num_i - log(exp(num_i) + sum_j exp(S*score_ij) - exp(S*target_i))
// out  = -mean(L),  S=30, m = {0:0.1, 1:0.4}[label]

#define NROWS 2048
#define CCOLS 50257
#define BLK   256

__device__ float g_rowL[NROWS];
__device__ unsigned int g_count = 0;   // self-resetting via atomicInc wrap

__device__ __forceinline__ float ex2f(float x) {
    float y;
    asm("ex2.approx.ftz.f32 %0, %1;" : "=f"(y) : "f"(x));
    return y;
}

__global__ __launch_bounds__(BLK) void amsm_kernel(
    const float* __restrict__ score,
    const int* __restrict__ labels,
    float* __restrict__ out)
{
    const int row = blockIdx.x;
    const int tid = threadIdx.x;
    const float* __restrict__ p = score + (size_t)row * CCOLS;

    const float SL2E = 30.0f * 1.44269504088896340736f; // S * log2(e)

    // Row base is (row mod 4) floats off 16B alignment (50257 % 4 == 1).
    const int peel = (4 - (row & 3)) & 3;

    float s0 = 0.f, s1 = 0.f, s2 = 0.f, s3 = 0.f;
    if (tid < peel) s0 += ex2f(SL2E * p[tid]);

    const int n4 = (CCOLS - peel) >> 2;
    const float4* __restrict__ q = (const float4*)(p + peel);

    int i = tid;
    // 2 x float4 in flight per thread
    for (; i + BLK < n4; i += 2 * BLK) {
        float4 a = q[i];
        float4 b = q[i + BLK];
        s0 += ex2f(SL2E * a.x); s1 += ex2f(SL2E * a.y);
        s2 += ex2f(SL2E * a.z); s3 += ex2f(SL2E * a.w);
        s0 += ex2f(SL2E * b.x); s1 += ex2f(SL2E * b.y);
        s2 += ex2f(SL2E * b.z); s3 += ex2f(SL2E * b.w);
    }
    for (; i < n4; i += BLK) {
        float4 a = q[i];
        s0 += ex2f(SL2E * a.x); s1 += ex2f(SL2E * a.y);
        s2 += ex2f(SL2E * a.z); s3 += ex2f(SL2E * a.w);
    }
    const int tail = peel + 4 * n4;        // CCOLS - tail < 4 leftover elems
    if (tid < CCOLS - tail) s0 += ex2f(SL2E * p[tail + tid]);

    float sum = (s0 + s1) + (s2 + s3);

    // Block reduction
    __shared__ float red[BLK];
    red[tid] = sum;
    __syncthreads();
    #pragma unroll
    for (int off = BLK / 2; off >= 32; off >>= 1) {
        if (tid < off) red[tid] += red[tid + off];
        __syncthreads();
    }

    __shared__ unsigned s_last;
    if (tid < 32) {
        float v = red[tid];
        #pragma unroll
        for (int off = 16; off > 0; off >>= 1)
            v += __shfl_down_sync(0xFFFFFFFFu, v, off);
        if (tid == 0) {
            int lab = labels[row] & 1;             // 0 or 1
            float m = lab ? 0.4f : 0.1f;
            float t = p[lab];                      // target logit
            float num = 30.0f * (t - m);
            float excl = v - ex2f(SL2E * t);       // sum minus target term
            float denom = ex2f(num * 1.44269504088896340736f) + excl;
            g_rowL[row] = num - logf(denom);
            __threadfence();
            // wraps to 0 when old == NROWS-1 -> self-resetting per replay
            unsigned old = atomicInc(&g_count, NROWS - 1);
            s_last = (old == NROWS - 1) ? 1u : 0u;
        }
    }
    __syncthreads();

    // Last-arriving block reduces all row losses and writes the output.
    if (s_last) {
        volatile float* rl = g_rowL;
        double acc = 0.0;
        for (int r = tid; r < NROWS; r += BLK)
            acc += (double)rl[r];
        __shared__ double dred[BLK];
        dred[tid] = acc;
        __syncthreads();
        #pragma unroll
        for (int off = BLK / 2; off > 0; off >>= 1) {
            if (tid < off) dred[tid] += dred[tid + off];
            __syncthreads();
        }
        if (tid == 0)
            out[0] = (float)(-dred[0] / (double)NROWS);
    }
}

extern "C" void kernel_launch(void* const* d_in, const int* in_sizes, int n_in,
                              void* d_out, int out_size)
{
    const float* score = (const float*)d_in[0];
    const int* labels = (const int*)d_in[1];
    float* out = (float*)d_out;

    amsm_kernel<<<NROWS, BLK>>>(score, labels, out);
}